// round 10
// baseline (speedup 1.0000x reference)
#include <cuda_runtime.h>
#include <cuda_bf16.h>
#include <cstdint>

#define NROWS 32768
#define DIM   512
#define KC    4096
#define NTILE_N 32
#define NTILES  (256 * NTILE_N)    // 256 m-tiles x 32 n-tiles
#define SLOTS   8
#define MARGIN  0.002f
#define TC_GRID 296

__device__ float g_wnorm[KC];
__device__ float g_xnorm[NROWS];
__device__ int   g_k[NROWS];
__device__ float g_partial[NROWS];
__device__ int   g_used[KC];
__device__ __nv_bfloat16 g_A16[NROWS * DIM];
__device__ __nv_bfloat16 g_B16[KC * DIM];
__device__ float         g_cval[(size_t)NTILE_N * NROWS * SLOTS];
__device__ int           g_cidx[(size_t)NTILE_N * NROWS * SLOTS];
__device__ unsigned char g_ccnt[(size_t)NTILE_N * NROWS];

// ---------------------------------------------------------------------------
__global__ void init_kernel() {
    int i = blockIdx.x * blockDim.x + threadIdx.x;
    if (i < KC) g_used[i] = 0;
}
__global__ void castA_kernel(const float* __restrict__ z) {
    int i = blockIdx.x * 256 + threadIdx.x;
    g_A16[i] = __float2bfloat16(z[i]);
}
__global__ void castB_kernel(const float* __restrict__ cb) {
    int i = blockIdx.x * 256 + threadIdx.x;
    g_B16[i] = __float2bfloat16(cb[i]);
}
// Exact sequential norms: acc = fl(acc + fl(v*v)) ascending d (validated r2-8).
__global__ void wnorm_kernel(const float* __restrict__ cb) {
    int code = blockIdx.x * blockDim.x + threadIdx.x;
    const float4* p = reinterpret_cast<const float4*>(cb + (size_t)code * DIM);
    float acc = 0.f;
    for (int i = 0; i < DIM / 4; i++) {
        float4 v = p[i];
        acc = __fadd_rn(acc, __fmul_rn(v.x, v.x));
        acc = __fadd_rn(acc, __fmul_rn(v.y, v.y));
        acc = __fadd_rn(acc, __fmul_rn(v.z, v.z));
        acc = __fadd_rn(acc, __fmul_rn(v.w, v.w));
    }
    g_wnorm[code] = acc;
}
__global__ void xnorm_kernel(const float* __restrict__ z) {
    int row = blockIdx.x * blockDim.x + threadIdx.x;
    const float4* p = reinterpret_cast<const float4*>(z + (size_t)row * DIM);
    float acc = 0.f;
    for (int i = 0; i < DIM / 4; i++) {
        float4 v = p[i];
        acc = __fadd_rn(acc, __fmul_rn(v.x, v.x));
        acc = __fadd_rn(acc, __fmul_rn(v.y, v.y));
        acc = __fadd_rn(acc, __fmul_rn(v.z, v.z));
        acc = __fadd_rn(acc, __fmul_rn(v.w, v.w));
    }
    g_xnorm[row] = acc;
}

// ---------------------------------------------------------------------------
__device__ __forceinline__ void cp16(const void* smem, const void* g) {
    uint32_t a = (uint32_t)__cvta_generic_to_shared(smem);
    asm volatile("cp.async.cg.shared.global [%0], [%1], 16;" :: "r"(a), "l"(g));
}
__device__ __forceinline__ void mma_bf16(float* c, const uint32_t* a, const uint32_t* b) {
    asm volatile(
        "mma.sync.aligned.m16n8k16.row.col.f32.bf16.bf16.f32 "
        "{%0,%1,%2,%3}, {%4,%5,%6,%7}, {%8,%9}, {%0,%1,%2,%3};"
        : "+f"(c[0]), "+f"(c[1]), "+f"(c[2]), "+f"(c[3])
        : "r"(a[0]), "r"(a[1]), "r"(a[2]), "r"(a[3]), "r"(b[0]), "r"(b[1]));
}

// ---------------------------------------------------------------------------
// Persistent bf16 HMMA GEMM (approx scores) + candidate epilogue.
// Tile 128x128, BK=64, 256 threads = 2x4 warps (warp tile 64x32).
// Smem rows padded to 72 bf16 (144B): conflict-free direct-LDS fragments.
#define BM 128
#define BN 128
#define BK 64
#define KSTEPS (DIM / BK)        // 8
#define STRIDE 72
#define BUF16 (2 * BM * STRIDE)  // bf16 per (A,B) buffer pair
#define TC_SMEM (2 * BUF16 * 2)  // bytes = 73728

extern __shared__ __nv_bfloat16 dsm16[];

__global__ void __launch_bounds__(256, 2) mma_gemm_kernel() {
    __shared__ float swn[128];
    __shared__ float s_v[128][4];
    __shared__ int   s_i[128][4];
    __shared__ float s_thr[128];
    __shared__ int   s_gx[128];
    __shared__ int   s_ctr[128];

    const int tid  = threadIdx.x;
    const int wid  = tid >> 5;
    const int lane = tid & 31;
    const int gid  = lane >> 2, ctid = lane & 3;
    const int wm   = wid >> 2,  wn   = wid & 3;

    for (int t = blockIdx.x; t < NTILES; t += TC_GRID) {
        const int m0  = (t >> 5) * BM;
        const int n0  = (t & 31) * BN;
        const int tci = t & 31;

        if (tid < 128) { swn[tid] = g_wnorm[n0 + tid]; s_ctr[tid] = 1; }

        float acc[4][4][4];
        #pragma unroll
        for (int a = 0; a < 4; a++)
            #pragma unroll
            for (int b = 0; b < 4; b++)
                #pragma unroll
                for (int c = 0; c < 4; c++) acc[a][b][c] = 0.f;

        auto prefetch = [&](int s) {
            __nv_bfloat16* Ab = dsm16 + (s & 1) * BUF16;
            __nv_bfloat16* Bb = Ab + BM * STRIDE;
            #pragma unroll
            for (int u = 0; u < 4; u++) {
                int idx = tid + u * 256;
                int r = idx >> 3, c = idx & 7;
                cp16(&Ab[r * STRIDE + c * 8],
                     &g_A16[(size_t)(m0 + r) * DIM + s * BK + c * 8]);
            }
            #pragma unroll
            for (int u = 0; u < 4; u++) {
                int idx = tid + u * 256;
                int r = idx >> 3, c = idx & 7;
                cp16(&Bb[r * STRIDE + c * 8],
                     &g_B16[(size_t)(n0 + r) * DIM + s * BK + c * 8]);
            }
        };

        prefetch(0);
        asm volatile("cp.async.commit_group;");

        for (int s = 0; s < KSTEPS; s++) {
            if (s + 1 < KSTEPS) {
                prefetch(s + 1);
                asm volatile("cp.async.commit_group;");
                asm volatile("cp.async.wait_group 1;");
            } else {
                asm volatile("cp.async.wait_group 0;");
            }
            __syncthreads();

            const __nv_bfloat16* Ab = dsm16 + (s & 1) * BUF16;
            const __nv_bfloat16* Bb = Ab + BM * STRIDE;
            #pragma unroll
            for (int kf = 0; kf < 4; kf++) {
                uint32_t afr[4][4], bfr[4][2];
                #pragma unroll
                for (int mf = 0; mf < 4; mf++) {
                    int r0 = wm * 64 + mf * 16 + gid;
                    const uint32_t* p0 = (const uint32_t*)&Ab[r0 * STRIDE + kf * 16 + ctid * 2];
                    const uint32_t* p1 = (const uint32_t*)&Ab[(r0 + 8) * STRIDE + kf * 16 + ctid * 2];
                    afr[mf][0] = p0[0]; afr[mf][1] = p1[0];
                    afr[mf][2] = p0[4]; afr[mf][3] = p1[4];
                }
                #pragma unroll
                for (int nf = 0; nf < 4; nf++) {
                    int n = wn * 32 + nf * 8 + gid;
                    const uint32_t* q = (const uint32_t*)&Bb[n * STRIDE + kf * 16 + ctid * 2];
                    bfr[nf][0] = q[0]; bfr[nf][1] = q[4];
                }
                #pragma unroll
                for (int mf = 0; mf < 4; mf++)
                    #pragma unroll
                    for (int nf = 0; nf < 4; nf++)
                        mma_bf16(acc[mf][nf], afr[mf], bfr[nf]);
            }
            __syncthreads();
        }

        // ---- epilogue: per-row min (quad shuffle) + 4-warp merge ----------
        #pragma unroll
        for (int mf = 0; mf < 4; mf++) {
            #pragma unroll
            for (int half = 0; half < 2; half++) {
                int rloc = wm * 64 + mf * 16 + gid + half * 8;
                float mv = 3.4e38f; int mi = 0x7fffffff;
                #pragma unroll
                for (int nf = 0; nf < 4; nf++) {
                    #pragma unroll
                    for (int e = 0; e < 2; e++) {
                        int cl = wn * 32 + nf * 8 + ctid * 2 + e;
                        float sc = swn[cl] - 2.0f * acc[mf][nf][half * 2 + e];
                        int gc = n0 + cl;
                        if (sc < mv || (sc == mv && gc < mi)) { mv = sc; mi = gc; }
                    }
                }
                #pragma unroll
                for (int off = 1; off <= 2; off <<= 1) {
                    float ov = __shfl_xor_sync(0xffffffffu, mv, off);
                    int   oi = __shfl_xor_sync(0xffffffffu, mi, off);
                    if (ov < mv || (ov == mv && oi < mi)) { mv = ov; mi = oi; }
                }
                if (ctid == 0) { s_v[rloc][wn] = mv; s_i[rloc][wn] = mi; }
            }
        }
        __syncthreads();
        if (tid < 128) {
            float gv = s_v[tid][0]; int gi = s_i[tid][0];
            #pragma unroll
            for (int w = 1; w < 4; w++) {
                float v = s_v[tid][w]; int i2 = s_i[tid][w];
                if (v < gv || (v == gv && i2 < gi)) { gv = v; gi = i2; }
            }
            size_t cb = ((size_t)tci * NROWS + m0 + tid) * SLOTS;
            g_cval[cb] = gv; g_cidx[cb] = gi;
            s_thr[tid] = gv + MARGIN; s_gx[tid] = gi;
        }
        __syncthreads();
        // candidate append (order-free; resolve uses (v,i) comparator)
        #pragma unroll
        for (int mf = 0; mf < 4; mf++) {
            #pragma unroll
            for (int half = 0; half < 2; half++) {
                int rloc = wm * 64 + mf * 16 + gid + half * 8;
                float thr = s_thr[rloc]; int gx = s_gx[rloc];
                #pragma unroll
                for (int nf = 0; nf < 4; nf++) {
                    #pragma unroll
                    for (int e = 0; e < 2; e++) {
                        int cl = wn * 32 + nf * 8 + ctid * 2 + e;
                        float sc = swn[cl] - 2.0f * acc[mf][nf][half * 2 + e];
                        int gc = n0 + cl;
                        if (sc < thr && gc != gx) {
                            int pos = atomicAdd(&s_ctr[rloc], 1);
                            if (pos < SLOTS) {
                                size_t cb = ((size_t)tci * NROWS + m0 + rloc) * SLOTS;
                                g_cval[cb + pos] = sc;
                                g_cidx[cb + pos] = gc;
                            }
                        }
                    }
                }
            }
        }
        __syncthreads();
        if (tid < 128) {
            int c = s_ctr[tid];
            g_ccnt[(size_t)tci * NROWS + m0 + tid] = (c > SLOTS) ? 255 : (unsigned char)c;
        }
        __syncthreads();
    }
}

// ---------------------------------------------------------------------------
// Exact reference-rounded score (bit-identical to validated rounds 2-8).
__device__ __forceinline__ float exact_ref_score(const float* __restrict__ zr,
                                                 const float* __restrict__ wr,
                                                 float xn, float wn) {
    float acc = 0.f;
    #pragma unroll 8
    for (int d = 0; d < DIM; d++)
        acc = __fmaf_rn(zr[d], wr[d], acc);
    float p = __fmul_rn(2.0f, acc);
    float q = __fsub_rn(xn, p);
    return __fadd_rn(q, wn);
}

// One warp per row: filter candidates, exact rescoring, (v,i) argmin.
__global__ void resolve_kernel(const float* __restrict__ z,
                               const float* __restrict__ cb) {
    const int lane = threadIdx.x & 31;
    const int row  = (blockIdx.x * blockDim.x + threadIdx.x) >> 5;
    const float xn = g_xnorm[row];
    const float* zr = z + (size_t)row * DIM;

    float v0 = g_cval[((size_t)lane * NROWS + row) * SLOTS];
    int cnt_l = g_ccnt[(size_t)lane * NROWS + row];
    float gm = v0;
    #pragma unroll
    for (int off = 16; off > 0; off >>= 1) {
        float o = __shfl_xor_sync(0xffffffffu, gm, off);
        if (o < gm) gm = o;
    }
    bool ovf = __ballot_sync(0xffffffffu, cnt_l == 255) != 0;

    float bv = 3.4e38f; int bi = 0x7fffffff;
    if (!ovf) {
        float thr = gm + MARGIN;
        for (int ti = lane; ti < NTILE_N * SLOTS; ti += 32) {
            int tt = ti >> 3, s = ti & 7;
            int cc = g_ccnt[(size_t)tt * NROWS + row];
            if (s < cc) {
                size_t e = ((size_t)tt * NROWS + row) * SLOTS + s;
                if (g_cval[e] < thr) {
                    int ci = g_cidx[e];
                    float r = exact_ref_score(zr, cb + (size_t)ci * DIM, xn, g_wnorm[ci]);
                    if (r < bv || (r == bv && ci < bi)) { bv = r; bi = ci; }
                }
            }
        }
    } else {
        for (int c = lane; c < KC; c += 32) {
            float r = exact_ref_score(zr, cb + (size_t)c * DIM, xn, g_wnorm[c]);
            if (r < bv || (r == bv && c < bi)) { bv = r; bi = c; }
        }
    }
    #pragma unroll
    for (int off = 16; off > 0; off >>= 1) {
        float ov = __shfl_xor_sync(0xffffffffu, bv, off);
        int   oi = __shfl_xor_sync(0xffffffffu, bi, off);
        if (ov < bv || (ov == bv && oi < bi)) { bv = ov; bi = oi; }
    }
    if (lane == 0) g_k[row] = bi;
}

// ---------------------------------------------------------------------------
__global__ void gather_kernel(const float* __restrict__ z,
                              const float* __restrict__ cb,
                              float* __restrict__ out) {
    __shared__ float red[128];
    int row = blockIdx.x;
    int t   = threadIdx.x;
    int k   = g_k[row];

    float4 w = reinterpret_cast<const float4*>(cb + (size_t)k   * DIM)[t];
    float4 x = reinterpret_cast<const float4*>(z  + (size_t)row * DIM)[t];

    float4 o;
    o.x = __fadd_rn(x.x, __fsub_rn(w.x, x.x));
    o.y = __fadd_rn(x.y, __fsub_rn(w.y, x.y));
    o.z = __fadd_rn(x.z, __fsub_rn(w.z, x.z));
    o.w = __fadd_rn(x.w, __fsub_rn(w.w, x.w));
    reinterpret_cast<float4*>(out + (size_t)row * DIM)[t] = o;

    float dx = __fsub_rn(x.x, w.x), dy = __fsub_rn(x.y, w.y);
    float dz = __fsub_rn(x.z, w.z), dw = __fsub_rn(x.w, w.w);
    red[t] = dx * dx + dy * dy + dz * dz + dw * dw;
    __syncthreads();
    #pragma unroll
    for (int off = 64; off > 0; off >>= 1) {
        if (t < off) red[t] += red[t + off];
        __syncthreads();
    }
    if (t == 0) {
        g_partial[row] = red[0];
        g_used[k] = 1;
        out[(size_t)NROWS * DIM + row] = (float)k;
    }
}

__global__ void finalize_kernel(float* __restrict__ out) {
    __shared__ double red[1024];
    int t = threadIdx.x;
    double s = 0.0;
    for (int i = t; i < NROWS; i += 1024) s += (double)g_partial[i];
    red[t] = s;
    __syncthreads();
    #pragma unroll
    for (int off = 512; off > 0; off >>= 1) {
        if (t < off) red[t] += red[t + off];
        __syncthreads();
    }
    double lossTotal = red[0];
    __syncthreads();
    double u = 0.0;
    for (int i = t; i < KC; i += 1024) u += (double)g_used[i];
    red[t] = u;
    __syncthreads();
    #pragma unroll
    for (int off = 512; off > 0; off >>= 1) {
        if (t < off) red[t] += red[t + off];
        __syncthreads();
    }
    if (t == 0) {
        size_t base = (size_t)NROWS * DIM + NROWS;
        out[base]     = (float)(0.25 * lossTotal / ((double)NROWS * (double)DIM));
        out[base + 1] = (float)(red[0] / (double)KC);
    }
}

// ---------------------------------------------------------------------------
extern "C" void kernel_launch(void* const* d_in, const int* in_sizes, int n_in,
                              void* d_out, int out_size) {
    const float* z  = (const float*)d_in[0];
    const float* cb = (const float*)d_in[1];
    if (in_sizes[0] == KC * DIM) { z = (const float*)d_in[1]; cb = (const float*)d_in[0]; }
    float* out = (float*)d_out;

    cudaFuncSetAttribute(mma_gemm_kernel,
                         cudaFuncAttributeMaxDynamicSharedMemorySize, TC_SMEM);

    init_kernel<<<(KC + 255) / 256, 256>>>();
    castA_kernel<<<(NROWS * DIM) / 256, 256>>>(z);
    castB_kernel<<<(KC * DIM) / 256, 256>>>(cb);
    wnorm_kernel<<<KC / 128, 128>>>(cb);
    xnorm_kernel<<<NROWS / 128, 128>>>(z);
    mma_gemm_kernel<<<TC_GRID, 256, TC_SMEM>>>();
    resolve_kernel<<<NROWS * 32 / 256, 256>>>(z, cb);
    gather_kernel<<<NROWS, 128>>>(z, cb, out);
    finalize_kernel<<<1, 1024>>>(out);
}

// round 11
// speedup vs baseline: 2.0005x; 2.0005x over previous
#include <cuda_runtime.h>
#include <cstdint>

// Fixed shapes: z_e [16,2048,512] -> N=32768 rows, codebook [4096,512]
#define NROWS 32768
#define DIM   512
#define KC    4096

__device__ float g_wnorm[KC];
__device__ float g_xnorm[NROWS];
__device__ float g_partial[NROWS];
__device__ int   g_used[KC];
// per-(chunk,row) partial argmin results
#define NCHUNK 8
__device__ float g_pval[NCHUNK * NROWS];
__device__ int   g_pidx[NCHUNK * NROWS];
// k-major transposed operands (sanctioned static scratch)
__device__ float g_AT[DIM * NROWS];   // AT[d][m] = z[m][d]      (64 MB)
__device__ float g_BT[DIM * KC];      // BT[d][n] = cb[n][d]     ( 8 MB)

// ---------------------------------------------------------------------------
// Tiled transposes: in[R][512] -> out[512][R]
__global__ void transposeA_kernel(const float* __restrict__ in) {
    __shared__ float tile[32][33];
    int c0 = blockIdx.x * 32, r0 = blockIdx.y * 32;
    #pragma unroll
    for (int i = threadIdx.y; i < 32; i += 8)
        tile[i][threadIdx.x] = in[(size_t)(r0 + i) * DIM + c0 + threadIdx.x];
    __syncthreads();
    #pragma unroll
    for (int i = threadIdx.y; i < 32; i += 8)
        g_AT[(size_t)(c0 + i) * NROWS + r0 + threadIdx.x] = tile[threadIdx.x][i];
}

// transposeB also zeroes g_used (folds the old init kernel -> vq_argmin is
// the 5th launch and lands in the ncu -s 5 -c 1 window).
__global__ void transposeB_kernel(const float* __restrict__ in) {
    __shared__ float tile[32][33];
    int lid = ((blockIdx.y * gridDim.x + blockIdx.x) * 256) +
              threadIdx.y * 32 + threadIdx.x;
    if (lid < KC) g_used[lid] = 0;
    int c0 = blockIdx.x * 32, r0 = blockIdx.y * 32;
    #pragma unroll
    for (int i = threadIdx.y; i < 32; i += 8)
        tile[i][threadIdx.x] = in[(size_t)(r0 + i) * DIM + c0 + threadIdx.x];
    __syncthreads();
    #pragma unroll
    for (int i = threadIdx.y; i < 32; i += 8)
        g_BT[(size_t)(c0 + i) * KC + r0 + threadIdx.x] = tile[threadIdx.x][i];
}

// ---------------------------------------------------------------------------
// ||w||^2 / ||x||^2 from the k-major arrays (coalesced): same sequential
// ascending-d scalar chain acc = fl(acc + fl(v*v)) -> bit-identical values.
__global__ void wnorm_kernel() {
    int code = blockIdx.x * blockDim.x + threadIdx.x;
    if (code >= KC) return;
    float acc = 0.f;
    for (int d = 0; d < DIM; d++) {
        float v = g_BT[(size_t)d * KC + code];
        acc = __fadd_rn(acc, __fmul_rn(v, v));
    }
    g_wnorm[code] = acc;
}

__global__ void xnorm_kernel() {
    int row = blockIdx.x * blockDim.x + threadIdx.x;
    if (row >= NROWS) return;
    float acc = 0.f;
    for (int d = 0; d < DIM; d++) {
        float v = g_AT[(size_t)d * NROWS + row];
        acc = __fadd_rn(acc, __fmul_rn(v, v));
    }
    g_xnorm[row] = acc;
}

// ---------------------------------------------------------------------------
// Packed f32x2: each 32-bit half is an independent IEEE fp32 FMA chain.
__device__ __forceinline__ unsigned long long dup2(float a) {
    unsigned long long r;
    asm("mov.b64 %0, {%1, %1};" : "=l"(r) : "f"(a));
    return r;
}
__device__ __forceinline__ void fma2(unsigned long long& d,
                                     unsigned long long a,
                                     unsigned long long b) {
    asm("fma.rn.f32x2 %0, %1, %2, %0;" : "+l"(d) : "l"(a), "l"(b));
}
union U64F2 { unsigned long long u; float2 f; };

__device__ __forceinline__ void cp16(uint32_t smem, const float* g) {
    asm volatile("cp.async.cg.shared.global [%0], [%1], 16;" :: "r"(smem), "l"(g));
}

// ---------------------------------------------------------------------------
// Persistent fused fp32 GEMM + argmin.
// Work = 4096 tiles: 512 row-tiles (BM=64) x 8 code-chunks (512 codes).
// grid = 304 CTAs (152 SMs x occ2): per-SM load 27 vs 26.9 avg -> 0.2% tail.
//  - dot per (row,code): single ascending-k FMA chain, bit-identical to all
//    passing rounds (2 chains per fma.rn.f32x2).
//  - score: d = fl( fl(xnorm - fl(2*dot)) + wnorm )
//  - argmin: (value,index) comparator; per-chunk partials merged in gather
//    over ascending disjoint ranges == jnp.argmin first-occurrence.
#define BM 64
#define BN 256
#define BK 16
#define TM 8
#define NTILES 4096
#define VQ_GRID 304
#define TSTAGES 64              // (512/BN) * (DIM/BK) = 2 * 32 per tile
#define A_STG (BK * BM)
#define B_STG (BK * BN)
#define SMEM_BYTES (3 * (A_STG + B_STG) * 4)   // 61440

extern __shared__ float dynsmem[];

__global__ void __launch_bounds__(128, 2)
vq_argmin_kernel() {
    float* As = dynsmem;                 // [3][BK][BM]
    float* Bs = dynsmem + 3 * A_STG;     // [3][BK][BN]

    const int tid = threadIdx.x;
    const int tx  = tid & 15;    // col group
    const int ty  = tid >> 4;    // row group (0..7)

    for (int t = blockIdx.x; t < NTILES; t += gridDim.x) {
        const int rowBase = (t >> 3) * BM;
        const int cbase0  = (t & 7) * (KC / NCHUNK);

        float xn[TM];
        #pragma unroll
        for (int i = 0; i < TM; i++) xn[i] = g_xnorm[rowBase + ty * TM + i];

        float bestV = 3.4e38f;   // carried on threads tx<8 (row ty*8+tx)
        int   bestI = 0x7fffffff;

        auto prefetch = [&](int s) {
            int b  = s % 3;
            int cb = cbase0 + (s >> 5) * BN;
            int dk = (s & 31) * BK;
            #pragma unroll
            for (int u = 0; u < 2; u++) {                 // A: 256 x 16B
                int idx = tid + u * 128;
                int k = idx >> 4, seg = (idx & 15) * 4;
                cp16((uint32_t)__cvta_generic_to_shared(&As[b * A_STG + k * BM + seg]),
                     &g_AT[(size_t)(dk + k) * NROWS + rowBase + seg]);
            }
            #pragma unroll
            for (int u = 0; u < 8; u++) {                 // B: 1024 x 16B
                int idx = tid + u * 128;
                int k = idx >> 6, seg = (idx & 63) * 4;
                cp16((uint32_t)__cvta_generic_to_shared(&Bs[b * B_STG + k * BN + seg]),
                     &g_BT[(size_t)(dk + k) * KC + cb + seg]);
            }
        };

        prefetch(0); asm volatile("cp.async.commit_group;");
        prefetch(1); asm volatile("cp.async.commit_group;");

        int sg = 0;
        for (int cb2 = 0; cb2 < 2; cb2++) {
            const int cbase = cbase0 + cb2 * BN;
            unsigned long long acc[TM][8];
            #pragma unroll
            for (int i = 0; i < TM; i++)
                #pragma unroll
                for (int p = 0; p < 8; p++) acc[i][p] = 0ull;

            for (int dk = 0; dk < DIM; dk += BK) {
                asm volatile("cp.async.wait_group 1;");
                __syncthreads();
                if (sg + 2 < TSTAGES) prefetch(sg + 2);
                asm volatile("cp.async.commit_group;");

                const float* Ab = &As[(sg % 3) * A_STG];
                const float* Bb = &Bs[(sg % 3) * B_STG];
                #pragma unroll
                for (int kk = 0; kk < BK; kk++) {
                    float a[TM];
                    *(float4*)&a[0] = *(const float4*)&Ab[kk * BM + ty * TM];
                    *(float4*)&a[4] = *(const float4*)&Ab[kk * BM + ty * TM + 4];
                    unsigned long long bq[8];
                    #pragma unroll
                    for (int j = 0; j < 4; j++) {
                        ulonglong2 b = *(const ulonglong2*)&Bb[kk * BN + 4 * (tx + 16 * j)];
                        bq[2 * j]     = b.x;
                        bq[2 * j + 1] = b.y;
                    }
                    #pragma unroll
                    for (int i = 0; i < TM; i++) {
                        unsigned long long ad = dup2(a[i]);
                        #pragma unroll
                        for (int p = 0; p < 8; p++)
                            fma2(acc[i][p], ad, bq[p]);
                    }
                }
                sg++;
            }

            // argmin epilogue: per-thread scan (reference rounding order),
            // 16-lane butterfly with (value,index) comparator.
            #pragma unroll
            for (int i = 0; i < TM; i++) {
                float mv = 3.4e38f; int mi = 0x7fffffff;
                #pragma unroll
                for (int j = 0; j < 4; j++) {
                    #pragma unroll
                    for (int h = 0; h < 2; h++) {
                        U64F2 u; u.u = acc[i][2 * j + h];
                        int c0 = cbase + 4 * (tx + 16 * j) + 2 * h;
                        float av[2] = { u.f.x, u.f.y };
                        #pragma unroll
                        for (int e = 0; e < 2; e++) {
                            int   col = c0 + e;
                            float p   = __fmul_rn(2.0f, av[e]);
                            float q   = __fsub_rn(xn[i], p);
                            float sc  = __fadd_rn(q, g_wnorm[col]);
                            if (sc < mv || (sc == mv && col < mi)) { mv = sc; mi = col; }
                        }
                    }
                }
                #pragma unroll
                for (int off = 8; off > 0; off >>= 1) {
                    float ov = __shfl_xor_sync(0xffffffffu, mv, off);
                    int   oi = __shfl_xor_sync(0xffffffffu, mi, off);
                    if (ov < mv || (ov == mv && oi < mi)) { mv = ov; mi = oi; }
                }
                if (tx == i) {
                    if (mv < bestV || (mv == bestV && mi < bestI)) { bestV = mv; bestI = mi; }
                }
            }
        }

        if (tx < TM) {
            int r = rowBase + ty * TM + tx;
            g_pval[(t & 7) * NROWS + r] = bestV;
            g_pidx[(t & 7) * NROWS + r] = bestI;
        }
        __syncthreads();   // drain: next tile's prefetch reuses smem buffers
    }
}

// ---------------------------------------------------------------------------
// Merge per-chunk partials (ascending disjoint ranges -> first-occurrence),
// gather z_q, ST output x + (z_q - x), loss partials, used flags, k as float.
__global__ void gather_kernel(const float* __restrict__ z,
                              const float* __restrict__ cb,
                              float* __restrict__ out) {
    __shared__ float red[128];
    int row = blockIdx.x;
    int t   = threadIdx.x;

    float bv = 3.4e38f; int k = 0x7fffffff;
    #pragma unroll
    for (int c = 0; c < NCHUNK; c++) {
        float v = g_pval[c * NROWS + row];
        int   i = g_pidx[c * NROWS + row];
        if (v < bv || (v == bv && i < k)) { bv = v; k = i; }
    }

    float4 w = reinterpret_cast<const float4*>(cb + (size_t)k   * DIM)[t];
    float4 x = reinterpret_cast<const float4*>(z  + (size_t)row * DIM)[t];

    float4 o;
    o.x = __fadd_rn(x.x, __fsub_rn(w.x, x.x));
    o.y = __fadd_rn(x.y, __fsub_rn(w.y, x.y));
    o.z = __fadd_rn(x.z, __fsub_rn(w.z, x.z));
    o.w = __fadd_rn(x.w, __fsub_rn(w.w, x.w));
    reinterpret_cast<float4*>(out + (size_t)row * DIM)[t] = o;

    float dx = __fsub_rn(x.x, w.x), dy = __fsub_rn(x.y, w.y);
    float dz = __fsub_rn(x.z, w.z), dw = __fsub_rn(x.w, w.w);
    red[t] = dx * dx + dy * dy + dz * dz + dw * dw;
    __syncthreads();
    #pragma unroll
    for (int off = 64; off > 0; off >>= 1) {
        if (t < off) red[t] += red[t + off];
        __syncthreads();
    }
    if (t == 0) {
        g_partial[row] = red[0];
        g_used[k] = 1;
        out[(size_t)NROWS * DIM + row] = (float)k;   // k segment
    }
}

// ---------------------------------------------------------------------------
__global__ void finalize_kernel(float* __restrict__ out) {
    __shared__ double red[1024];
    int t = threadIdx.x;

    double s = 0.0;
    for (int i = t; i < NROWS; i += 1024) s += (double)g_partial[i];
    red[t] = s;
    __syncthreads();
    #pragma unroll
    for (int off = 512; off > 0; off >>= 1) {
        if (t < off) red[t] += red[t + off];
        __syncthreads();
    }
    double lossTotal = red[0];
    __syncthreads();

    double u = 0.0;
    for (int i = t; i < KC; i += 1024) u += (double)g_used[i];
    red[t] = u;
    __syncthreads();
    #pragma unroll
    for (int off = 512; off > 0; off >>= 1) {
        if (t < off) red[t] += red[t + off];
        __syncthreads();
    }

    if (t == 0) {
        size_t base = (size_t)NROWS * DIM + NROWS;
        out[base]     = (float)(0.25 * lossTotal / ((double)NROWS * (double)DIM));
        out[base + 1] = (float)(red[0] / (double)KC);
    }
}

// ---------------------------------------------------------------------------
extern "C" void kernel_launch(void* const* d_in, const int* in_sizes, int n_in,
                              void* d_out, int out_size) {
    const float* z  = (const float*)d_in[0];   // z_e [32768, 512]
    const float* cb = (const float*)d_in[1];   // codebook [4096, 512]
    if (in_sizes[0] == KC * DIM) {             // defensive: swap if order differs
        z  = (const float*)d_in[1];
        cb = (const float*)d_in[0];
    }
    float* out = (float*)d_out;                // [z_q_st | k | vq_loss | utilization]

    cudaFuncSetAttribute(vq_argmin_kernel,
                         cudaFuncAttributeMaxDynamicSharedMemorySize, SMEM_BYTES);

    {
        dim3 blk(32, 8);
        transposeA_kernel<<<dim3(DIM / 32, NROWS / 32), blk>>>(z);   // launch 1
        transposeB_kernel<<<dim3(DIM / 32, KC / 32),   blk>>>(cb);   // launch 2 (+g_used init)
    }
    wnorm_kernel<<<64, 64>>>();                                      // launch 3
    xnorm_kernel<<<NROWS / 128, 128>>>();                            // launch 4
    vq_argmin_kernel<<<VQ_GRID, 128, SMEM_BYTES>>>();                // launch 5 (profiled)
    gather_kernel<<<NROWS, 128>>>(z, cb, out);
    finalize_kernel<<<1, 1024>>>(out);
}

// round 12
// speedup vs baseline: 2.0237x; 1.0116x over previous
#include <cuda_runtime.h>
#include <cstdint>

// Fixed shapes: z_e [16,2048,512] -> N=32768 rows, codebook [4096,512]
#define NROWS 32768
#define DIM   512
#define KC    4096

__device__ float g_wnorm[KC];
__device__ float g_xnorm[NROWS];
__device__ float g_partial[NROWS];
__device__ int   g_used[KC];
// per-(chunk,row) partial argmin results
#define NCHUNK 16
__device__ float g_pval[NCHUNK * NROWS];
__device__ int   g_pidx[NCHUNK * NROWS];
// k-major transposed operands (sanctioned static scratch)
__device__ float g_AT[DIM * NROWS];   // AT[d][m] = z[m][d]      (64 MB)
__device__ float g_BT[DIM * KC];      // BT[d][n] = cb[n][d]     ( 8 MB)

// ---------------------------------------------------------------------------
// Tiled transposes: in[R][512] -> out[512][R]
__global__ void transposeA_kernel(const float* __restrict__ in) {
    __shared__ float tile[32][33];
    int c0 = blockIdx.x * 32, r0 = blockIdx.y * 32;
    #pragma unroll
    for (int i = threadIdx.y; i < 32; i += 8)
        tile[i][threadIdx.x] = in[(size_t)(r0 + i) * DIM + c0 + threadIdx.x];
    __syncthreads();
    #pragma unroll
    for (int i = threadIdx.y; i < 32; i += 8)
        g_AT[(size_t)(c0 + i) * NROWS + r0 + threadIdx.x] = tile[threadIdx.x][i];
}

// transposeB also zeroes g_used (folded init).
__global__ void transposeB_kernel(const float* __restrict__ in) {
    __shared__ float tile[32][33];
    int lid = ((blockIdx.y * gridDim.x + blockIdx.x) * 256) +
              threadIdx.y * 32 + threadIdx.x;
    if (lid < KC) g_used[lid] = 0;
    int c0 = blockIdx.x * 32, r0 = blockIdx.y * 32;
    #pragma unroll
    for (int i = threadIdx.y; i < 32; i += 8)
        tile[i][threadIdx.x] = in[(size_t)(r0 + i) * DIM + c0 + threadIdx.x];
    __syncthreads();
    #pragma unroll
    for (int i = threadIdx.y; i < 32; i += 8)
        g_BT[(size_t)(c0 + i) * KC + r0 + threadIdx.x] = tile[threadIdx.x][i];
}

// ---------------------------------------------------------------------------
// Fused ||w||^2 + ||x||^2 (coalesced column reads from the k-major arrays):
// same sequential ascending-d scalar chain acc = fl(acc + fl(v*v)) per element
// -> bit-identical values; the two latency-bound loops now run concurrently.
#define WBLK 32
__global__ void norms_kernel() {
    int b = blockIdx.x;
    if (b < WBLK) {
        int code = b * 128 + threadIdx.x;      // 32*128 = 4096 codes
        float acc = 0.f;
        #pragma unroll 8
        for (int d = 0; d < DIM; d++) {
            float v = g_BT[(size_t)d * KC + code];
            acc = __fadd_rn(acc, __fmul_rn(v, v));
        }
        g_wnorm[code] = acc;
    } else {
        int row = (b - WBLK) * 128 + threadIdx.x;   // 256*128 = 32768 rows
        float acc = 0.f;
        #pragma unroll 8
        for (int d = 0; d < DIM; d++) {
            float v = g_AT[(size_t)d * NROWS + row];
            acc = __fadd_rn(acc, __fmul_rn(v, v));
        }
        g_xnorm[row] = acc;
    }
}

// ---------------------------------------------------------------------------
// Packed f32x2: each 32-bit half is an independent IEEE fp32 FMA chain.
__device__ __forceinline__ unsigned long long dup2(float a) {
    unsigned long long r;
    asm("mov.b64 %0, {%1, %1};" : "=l"(r) : "f"(a));
    return r;
}
__device__ __forceinline__ void fma2(unsigned long long& d,
                                     unsigned long long a,
                                     unsigned long long b) {
    asm("fma.rn.f32x2 %0, %1, %2, %0;" : "+l"(d) : "l"(a), "l"(b));
}
union U64F2 { unsigned long long u; float2 f; };

__device__ __forceinline__ void cp16(uint32_t smem, const float* g) {
    asm volatile("cp.async.cg.shared.global [%0], [%1], 16;" :: "r"(smem), "l"(g));
}

// ---------------------------------------------------------------------------
// Persistent fused fp32 GEMM + argmin.
// Work = 8192 tiles: 512 row-tiles (BM=64) x 16 code-chunks (BN=256 codes).
// grid = 304 CTAs: per-CTA load 27 vs 26.95 avg -> 0.37% tail quantization.
//  - dot per (row,code): single ascending-k FMA chain, bit-identical to all
//    passing rounds (2 chains per fma.rn.f32x2).
//  - score: d = fl( fl(xnorm - fl(2*dot)) + wnorm )
//  - argmin: (value,index) comparator; per-chunk partials merged in gather
//    over ascending disjoint ranges == jnp.argmin first-occurrence.
#define BM 64
#define BN 256
#define BK 16
#define TM 8
#define NTILES 8192
#define VQ_GRID 304
#define TSTAGES 32              // DIM/BK stages per tile (one 256-code chunk)
#define A_STG (BK * BM)
#define B_STG (BK * BN)
#define SMEM_BYTES (3 * (A_STG + B_STG) * 4)   // 61440

extern __shared__ float dynsmem[];

__global__ void __launch_bounds__(128, 2)
vq_argmin_kernel() {
    float* As = dynsmem;                 // [3][BK][BM]
    float* Bs = dynsmem + 3 * A_STG;     // [3][BK][BN]

    const int tid = threadIdx.x;
    const int tx  = tid & 15;    // col group
    const int ty  = tid >> 4;    // row group (0..7)

    for (int t = blockIdx.x; t < NTILES; t += gridDim.x) {
        const int rowBase = (t >> 4) * BM;
        const int cbase   = (t & 15) * BN;

        float xn[TM];
        #pragma unroll
        for (int i = 0; i < TM; i++) xn[i] = g_xnorm[rowBase + ty * TM + i];

        auto prefetch = [&](int s) {
            int b  = s % 3;
            int dk = s * BK;
            #pragma unroll
            for (int u = 0; u < 2; u++) {                 // A: 256 x 16B
                int idx = tid + u * 128;
                int k = idx >> 4, seg = (idx & 15) * 4;
                cp16((uint32_t)__cvta_generic_to_shared(&As[b * A_STG + k * BM + seg]),
                     &g_AT[(size_t)(dk + k) * NROWS + rowBase + seg]);
            }
            #pragma unroll
            for (int u = 0; u < 8; u++) {                 // B: 1024 x 16B
                int idx = tid + u * 128;
                int k = idx >> 6, seg = (idx & 63) * 4;
                cp16((uint32_t)__cvta_generic_to_shared(&Bs[b * B_STG + k * BN + seg]),
                     &g_BT[(size_t)(dk + k) * KC + cbase + seg]);
            }
        };

        prefetch(0); asm volatile("cp.async.commit_group;");
        prefetch(1); asm volatile("cp.async.commit_group;");

        unsigned long long acc[TM][8];
        #pragma unroll
        for (int i = 0; i < TM; i++)
            #pragma unroll
            for (int p = 0; p < 8; p++) acc[i][p] = 0ull;

        for (int sg = 0; sg < TSTAGES; sg++) {
            asm volatile("cp.async.wait_group 1;");
            __syncthreads();
            if (sg + 2 < TSTAGES) prefetch(sg + 2);
            asm volatile("cp.async.commit_group;");

            const float* Ab = &As[(sg % 3) * A_STG];
            const float* Bb = &Bs[(sg % 3) * B_STG];
            #pragma unroll
            for (int kk = 0; kk < BK; kk++) {
                float a[TM];
                *(float4*)&a[0] = *(const float4*)&Ab[kk * BM + ty * TM];
                *(float4*)&a[4] = *(const float4*)&Ab[kk * BM + ty * TM + 4];
                unsigned long long bq[8];
                #pragma unroll
                for (int j = 0; j < 4; j++) {
                    ulonglong2 b = *(const ulonglong2*)&Bb[kk * BN + 4 * (tx + 16 * j)];
                    bq[2 * j]     = b.x;
                    bq[2 * j + 1] = b.y;
                }
                #pragma unroll
                for (int i = 0; i < TM; i++) {
                    unsigned long long ad = dup2(a[i]);
                    #pragma unroll
                    for (int p = 0; p < 8; p++)
                        fma2(acc[i][p], ad, bq[p]);
                }
            }
        }

        // argmin epilogue: per-thread scan (reference rounding order),
        // 16-lane butterfly with (value,index) comparator.
        float bestV = 3.4e38f;   // valid on threads tx<8 (row ty*8+tx)
        int   bestI = 0x7fffffff;
        #pragma unroll
        for (int i = 0; i < TM; i++) {
            float mv = 3.4e38f; int mi = 0x7fffffff;
            #pragma unroll
            for (int j = 0; j < 4; j++) {
                #pragma unroll
                for (int h = 0; h < 2; h++) {
                    U64F2 u; u.u = acc[i][2 * j + h];
                    int c0 = cbase + 4 * (tx + 16 * j) + 2 * h;
                    float av[2] = { u.f.x, u.f.y };
                    #pragma unroll
                    for (int e = 0; e < 2; e++) {
                        int   col = c0 + e;
                        float p   = __fmul_rn(2.0f, av[e]);
                        float q   = __fsub_rn(xn[i], p);
                        float sc  = __fadd_rn(q, g_wnorm[col]);
                        if (sc < mv || (sc == mv && col < mi)) { mv = sc; mi = col; }
                    }
                }
            }
            #pragma unroll
            for (int off = 8; off > 0; off >>= 1) {
                float ov = __shfl_xor_sync(0xffffffffu, mv, off);
                int   oi = __shfl_xor_sync(0xffffffffu, mi, off);
                if (ov < mv || (ov == mv && oi < mi)) { mv = ov; mi = oi; }
            }
            if (tx == i) { bestV = mv; bestI = mi; }
        }

        if (tx < TM) {
            int r = rowBase + ty * TM + tx;
            g_pval[(t & 15) * NROWS + r] = bestV;
            g_pidx[(t & 15) * NROWS + r] = bestI;
        }
        __syncthreads();   // drain: next tile's prefetch reuses smem buffers
    }
}

// ---------------------------------------------------------------------------
// Merge per-chunk partials (ascending disjoint ranges -> first-occurrence),
// gather z_q, ST output x + (z_q - x), loss partials, used flags, k as float.
__global__ void gather_kernel(const float* __restrict__ z,
                              const float* __restrict__ cb,
                              float* __restrict__ out) {
    __shared__ float red[128];
    int row = blockIdx.x;
    int t   = threadIdx.x;

    float bv = 3.4e38f; int k = 0x7fffffff;
    #pragma unroll
    for (int c = 0; c < NCHUNK; c++) {
        float v = g_pval[c * NROWS + row];
        int   i = g_pidx[c * NROWS + row];
        if (v < bv || (v == bv && i < k)) { bv = v; k = i; }
    }

    float4 w = reinterpret_cast<const float4*>(cb + (size_t)k   * DIM)[t];
    float4 x = reinterpret_cast<const float4*>(z  + (size_t)row * DIM)[t];

    float4 o;
    o.x = __fadd_rn(x.x, __fsub_rn(w.x, x.x));
    o.y = __fadd_rn(x.y, __fsub_rn(w.y, x.y));
    o.z = __fadd_rn(x.z, __fsub_rn(w.z, x.z));
    o.w = __fadd_rn(x.w, __fsub_rn(w.w, x.w));
    reinterpret_cast<float4*>(out + (size_t)row * DIM)[t] = o;

    float dx = __fsub_rn(x.x, w.x), dy = __fsub_rn(x.y, w.y);
    float dz = __fsub_rn(x.z, w.z), dw = __fsub_rn(x.w, w.w);
    red[t] = dx * dx + dy * dy + dz * dz + dw * dw;
    __syncthreads();
    #pragma unroll
    for (int off = 64; off > 0; off >>= 1) {
        if (t < off) red[t] += red[t + off];
        __syncthreads();
    }
    if (t == 0) {
        g_partial[row] = red[0];
        g_used[k] = 1;
        out[(size_t)NROWS * DIM + row] = (float)k;   // k segment
    }
}

// ---------------------------------------------------------------------------
__global__ void finalize_kernel(float* __restrict__ out) {
    __shared__ double red[1024];
    int t = threadIdx.x;

    double s = 0.0;
    for (int i = t; i < NROWS; i += 1024) s += (double)g_partial[i];
    red[t] = s;
    __syncthreads();
    #pragma unroll
    for (int off = 512; off > 0; off >>= 1) {
        if (t < off) red[t] += red[t + off];
        __syncthreads();
    }
    double lossTotal = red[0];
    __syncthreads();

    double u = 0.0;
    for (int i = t; i < KC; i += 1024) u += (double)g_used[i];
    red[t] = u;
    __syncthreads();
    #pragma unroll
    for (int off = 512; off > 0; off >>= 1) {
        if (t < off) red[t] += red[t + off];
        __syncthreads();
    }

    if (t == 0) {
        size_t base = (size_t)NROWS * DIM + NROWS;
        out[base]     = (float)(0.25 * lossTotal / ((double)NROWS * (double)DIM));
        out[base + 1] = (float)(red[0] / (double)KC);
    }
}

// ---------------------------------------------------------------------------
extern "C" void kernel_launch(void* const* d_in, const int* in_sizes, int n_in,
                              void* d_out, int out_size) {
    const float* z  = (const float*)d_in[0];   // z_e [32768, 512]
    const float* cb = (const float*)d_in[1];   // codebook [4096, 512]
    if (in_sizes[0] == KC * DIM) {             // defensive: swap if order differs
        z  = (const float*)d_in[1];
        cb = (const float*)d_in[0];
    }
    float* out = (float*)d_out;                // [z_q_st | k | vq_loss | utilization]

    cudaFuncSetAttribute(vq_argmin_kernel,
                         cudaFuncAttributeMaxDynamicSharedMemorySize, SMEM_BYTES);

    {
        dim3 blk(32, 8);
        transposeA_kernel<<<dim3(DIM / 32, NROWS / 32), blk>>>(z);   // launch 1
        transposeB_kernel<<<dim3(DIM / 32, KC / 32),   blk>>>(cb);   // launch 2 (+g_used init)
    }
    norms_kernel<<<WBLK + NROWS / 128, 128>>>();                     // launch 3 (fused w+x)
    vq_argmin_kernel<<<VQ_GRID, 128, SMEM_BYTES>>>();                // launch 4
    gather_kernel<<<NROWS, 128>>>(z, cb, out);                       // launch 5 (profiled)
    finalize_kernel<<<1, 1024>>>(out);
}